// round 6
// baseline (speedup 1.0000x reference)
#include <cuda_runtime.h>
#include <cuda_fp16.h>
#include <cstdint>

#define NN 100000
#define EE 1600000
#define NE_TOT (EE + NN)          // edges incl. self loops
#define H4 4
#define HC1 64                     // H*C1 (layer1 per-node feat)
#define NOUT 64
#define HN2 256                    // H*NOUT (layer2 per-node feat)
#define NEG_SLOPE 0.2f

#define SCAN_CHUNK 2048
#define SCAN_NBLK ((NN + SCAN_CHUNK - 1) / SCAN_CHUNK)   // 49

// ---------------- scratch (device globals; no allocation allowed) ----------
__device__ __half g_xl1h[(size_t)NN * HC1];
__device__ __half g_xr1h[(size_t)NN * HC1];
__device__ float  g_h   [(size_t)NN * HC1];
__device__ __half g_xl2h[(size_t)NN * HN2];
__device__ __half g_xr2h[(size_t)NN * HN2];
__device__ int    g_eidx[2 * EE];
__device__ int    g_is64;
__device__ int    g_deg[NN];
__device__ int    g_rs [NN + 1];
__device__ int    g_cur[NN];
__device__ int    g_csr[NE_TOT];
__device__ int    g_bsum[SCAN_NBLK];
__device__ int    g_boff[SCAN_NBLK];

// ---------------- edge-index dtype detection + normalization ---------------
__global__ void detect_kernel(const void* p) {
    if (threadIdx.x == 0 && blockIdx.x == 0) {
        const long long* q = (const long long*)p;
        int is64 = 1;
        for (int i = 0; i < 256; i++) {
            long long v = q[i];
            if (v < 0 || v >= NN) { is64 = 0; break; }
        }
        g_is64 = is64;
    }
}

// deg[i] starts at 1 (self loop)
__global__ void init_deg_kernel() {
    int i = blockIdx.x * blockDim.x + threadIdx.x;
    if (i < NN) g_deg[i] = 1;
}

__global__ void convert_hist_kernel(const void* p) {
    int idx = blockIdx.x * blockDim.x + threadIdx.x;
    if (idx >= 2 * EE) return;
    int v;
    if (g_is64) v = (int)((const long long*)p)[idx];
    else        v = ((const int*)p)[idx];
    g_eidx[idx] = v;
    if (idx >= EE) atomicAdd(g_deg + v, 1);
}

// ---------------- parallel exclusive scan of g_deg --------------------------
__global__ __launch_bounds__(256) void scan_phase1() {
    int t = threadIdx.x;
    int base = blockIdx.x * SCAN_CHUNK + t * 8;
    int s = 0;
    #pragma unroll
    for (int k = 0; k < 8; k++) {
        int i = base + k;
        if (i < NN) s += g_deg[i];
    }
    #pragma unroll
    for (int off = 16; off; off >>= 1)
        s += __shfl_xor_sync(0xffffffffu, s, off);
    __shared__ int ws[8];
    if ((t & 31) == 0) ws[t >> 5] = s;
    __syncthreads();
    if (t == 0) {
        int tot = 0;
        #pragma unroll
        for (int w = 0; w < 8; w++) tot += ws[w];
        g_bsum[blockIdx.x] = tot;
    }
}

__global__ void scan_phase2() {
    if (threadIdx.x == 0) {
        int run = 0;
        for (int b = 0; b < SCAN_NBLK; b++) {
            g_boff[b] = run;
            run += g_bsum[b];
        }
        g_rs[NN] = run;
    }
}

__global__ __launch_bounds__(256) void scan_phase3() {
    int t = threadIdx.x;
    int lane = t & 31, wid = t >> 5;
    int base = blockIdx.x * SCAN_CHUNK + t * 8;

    int d[8]; int s = 0;
    #pragma unroll
    for (int k = 0; k < 8; k++) {
        int i = base + k;
        d[k] = (i < NN) ? g_deg[i] : 0;
        s += d[k];
    }
    int inc = s;
    #pragma unroll
    for (int off = 1; off < 32; off <<= 1) {
        int v = __shfl_up_sync(0xffffffffu, inc, off);
        if (lane >= off) inc += v;
    }
    __shared__ int wtot[8];
    if (lane == 31) wtot[wid] = inc;
    __syncthreads();
    int woff = 0;
    #pragma unroll
    for (int w = 0; w < 8; w++) if (w < wid) woff += wtot[w];
    int run = g_boff[blockIdx.x] + woff + (inc - s);
    #pragma unroll
    for (int k = 0; k < 8; k++) {
        int i = base + k;
        if (i < NN) { g_rs[i] = run; g_cur[i] = run; }
        run += d[k];
    }
}

__global__ void scatter_kernel() {
    int idx = blockIdx.x * blockDim.x + threadIdx.x;
    if (idx >= NE_TOT) return;
    int s, d;
    if (idx < EE) { s = g_eidx[idx]; d = g_eidx[EE + idx]; }
    else          { s = idx - EE; d = s; }
    int pos = atomicAdd(g_cur + d, 1);
    g_csr[pos] = s;
}

// ---------------- tensor-core GEMM (tf32 mma): Y(half) = X@W + B -----------
__device__ __forceinline__ unsigned f2tf32(float f) {
    unsigned u;
    asm("cvt.rna.tf32.f32 %0, %1;" : "=r"(u) : "f"(f));
    return u;
}

__device__ __forceinline__ void mma_tf32(float* c, const unsigned* a, const unsigned* b) {
    asm volatile(
        "mma.sync.aligned.m16n8k8.row.col.f32.tf32.tf32.f32 "
        "{%0,%1,%2,%3}, {%4,%5,%6,%7}, {%8,%9}, {%0,%1,%2,%3};\n"
        : "+f"(c[0]), "+f"(c[1]), "+f"(c[2]), "+f"(c[3])
        : "r"(a[0]), "r"(a[1]), "r"(a[2]), "r"(a[3]), "r"(b[0]), "r"(b[1]));
}

__global__ __launch_bounds__(256) void gemm_tc_h(
    const float* __restrict__ X, const float* __restrict__ W,
    const float* __restrict__ Bi, __half* __restrict__ Y, int n, int M)
{
    __shared__ unsigned as_[128][36];
    __shared__ unsigned bs[64][72];
    const int n0 = blockIdx.x * 128;
    const int m0 = blockIdx.y * 64;
    const int tid = threadIdx.x;
    const int lane = tid & 31, w = tid >> 5;
    const int wr = w >> 1, wc = w & 1;
    const int l4 = lane >> 2, lm4 = lane & 3;

    #pragma unroll
    for (int it = 0; it < 4; it++) {
        int idx = tid + it * 256;
        int k = idx >> 4, c4 = (idx & 15) * 4;
        float4 v = *(const float4*)&W[(size_t)k * M + m0 + c4];
        bs[k][c4]     = f2tf32(v.x);
        bs[k][c4 + 1] = f2tf32(v.y);
        bs[k][c4 + 2] = f2tf32(v.z);
        bs[k][c4 + 3] = f2tf32(v.w);
    }

    float c[2][4][4];
    #pragma unroll
    for (int mi = 0; mi < 2; mi++)
        #pragma unroll
        for (int ni = 0; ni < 4; ni++)
            #pragma unroll
            for (int q = 0; q < 4; q++) c[mi][ni][q] = 0.f;

    #pragma unroll
    for (int half = 0; half < 2; half++) {
        if (half) __syncthreads();
        #pragma unroll
        for (int it = 0; it < 4; it++) {
            int idx = tid + it * 256;
            int r = idx >> 3, c4 = (idx & 7) * 4;
            float4 v;
            if (n0 + r < n) v = *(const float4*)&X[(size_t)(n0 + r) * 64 + half * 32 + c4];
            else            v = make_float4(0.f, 0.f, 0.f, 0.f);
            as_[r][c4]     = f2tf32(v.x);
            as_[r][c4 + 1] = f2tf32(v.y);
            as_[r][c4 + 2] = f2tf32(v.z);
            as_[r][c4 + 3] = f2tf32(v.w);
        }
        __syncthreads();
        #pragma unroll
        for (int kk = 0; kk < 4; kk++) {
            int k0 = kk * 8;
            int kg = half * 32 + k0;
            unsigned a[2][4], b[4][2];
            #pragma unroll
            for (int mi = 0; mi < 2; mi++) {
                int rb = wr * 32 + mi * 16;
                a[mi][0] = as_[rb + l4][k0 + lm4];
                a[mi][1] = as_[rb + 8 + l4][k0 + lm4];
                a[mi][2] = as_[rb + l4][k0 + 4 + lm4];
                a[mi][3] = as_[rb + 8 + l4][k0 + 4 + lm4];
            }
            #pragma unroll
            for (int ni = 0; ni < 4; ni++) {
                int cb = wc * 32 + ni * 8;
                b[ni][0] = bs[kg + lm4][cb + l4];
                b[ni][1] = bs[kg + 4 + lm4][cb + l4];
            }
            #pragma unroll
            for (int mi = 0; mi < 2; mi++)
                #pragma unroll
                for (int ni = 0; ni < 4; ni++)
                    mma_tf32(c[mi][ni], a[mi], b[ni]);
        }
    }

    #pragma unroll
    for (int mi = 0; mi < 2; mi++) {
        #pragma unroll
        for (int rr = 0; rr < 2; rr++) {
            int node = n0 + wr * 32 + mi * 16 + rr * 8 + l4;
            if (node < n) {
                #pragma unroll
                for (int ni = 0; ni < 4; ni++) {
                    int col = wc * 32 + ni * 8 + 2 * lm4;
                    float v0 = c[mi][ni][rr * 2 + 0] + Bi[m0 + col];
                    float v1 = c[mi][ni][rr * 2 + 1] + Bi[m0 + col + 1];
                    __half2 hh = __floats2half2_rn(v0, v1);
                    *(__half2*)&Y[(size_t)node * M + m0 + col] = hh;
                }
            }
        }
    }
}

__device__ __forceinline__ float lrelu(float v) { return v > 0.f ? v : NEG_SLOPE * v; }

// ---------------- layer-1: one warp per node (CSR, atomic-free) -------------
__global__ __launch_bounds__(256) void edge1_node_kernel(
    const float* __restrict__ att, const float* __restrict__ bo)
{
    int node = (blockIdx.x * 256 + threadIdx.x) >> 5;
    if (node >= NN) return;
    int lane = threadIdx.x & 31;
    int c0 = lane * 2;

    float2 xr = __half22float2(*(const __half2*)(g_xr1h + (size_t)node * HC1 + c0));
    float  a0 = att[c0], a1 = att[c0 + 1];

    float accx = 0.f, accy = 0.f, den = 0.f;
    int rs = g_rs[node], re = g_rs[node + 1];
    for (int base = rs; base < re; base += 32) {
        int m = re - base;
        int sj = (lane < m) ? g_csr[base + lane] : 0;
        int jmax = (m < 32) ? m : 32;
        int j = 0;
        // 4-wide: issue all 4 gathers before any dependent work
        for (; j + 3 < jmax; j += 4) {
            int s[4];
            float2 xl[4];
            #pragma unroll
            for (int u = 0; u < 4; u++)
                s[u] = __shfl_sync(0xffffffffu, sj, j + u);
            #pragma unroll
            for (int u = 0; u < 4; u++)
                xl[u] = __half22float2(*(const __half2*)(g_xl1h + (size_t)s[u] * HC1 + c0));
            float p[4];
            #pragma unroll
            for (int u = 0; u < 4; u++)
                p[u] = fmaf(a0, lrelu(xl[u].x + xr.x), a1 * lrelu(xl[u].y + xr.y));
            #pragma unroll
            for (int u = 0; u < 4; u++) p[u] += __shfl_xor_sync(0xffffffffu, p[u], 4);
            #pragma unroll
            for (int u = 0; u < 4; u++) p[u] += __shfl_xor_sync(0xffffffffu, p[u], 2);
            #pragma unroll
            for (int u = 0; u < 4; u++) p[u] += __shfl_xor_sync(0xffffffffu, p[u], 1);
            #pragma unroll
            for (int u = 0; u < 4; u++) {
                float ex = __expf(p[u]);
                accx = fmaf(ex, xl[u].x, accx);
                accy = fmaf(ex, xl[u].y, accy);
                den += ex;
            }
        }
        for (; j < jmax; j++) {
            int s0 = __shfl_sync(0xffffffffu, sj, j);
            float2 xlA = __half22float2(*(const __half2*)(g_xl1h + (size_t)s0 * HC1 + c0));
            float pA = fmaf(a0, lrelu(xlA.x + xr.x), a1 * lrelu(xlA.y + xr.y));
            pA += __shfl_xor_sync(0xffffffffu, pA, 4);
            pA += __shfl_xor_sync(0xffffffffu, pA, 2);
            pA += __shfl_xor_sync(0xffffffffu, pA, 1);
            float exA = __expf(pA);
            accx = fmaf(exA, xlA.x, accx); accy = fmaf(exA, xlA.y, accy);
            den += exA;
        }
    }
    float inv = 1.f / (den + 1e-16f);
    float v0 = accx * inv + bo[c0];
    float v1 = accy * inv + bo[c0 + 1];
    size_t o = (size_t)node * HC1 + c0;
    g_h[o]     = v0 > 0.f ? v0 : 0.f;
    g_h[o + 1] = v1 > 0.f ? v1 : 0.f;
}

// ---------------- layer-2: one warp per node, all 4 heads per warp ----------
__device__ __forceinline__ void half8_to_f(const __half* p, float* f) {
    uint4 raw = *(const uint4*)p;
    const __half2* hp = (const __half2*)&raw;
    #pragma unroll
    for (int i = 0; i < 4; i++) {
        float2 t = __half22float2(hp[i]);
        f[2 * i] = t.x; f[2 * i + 1] = t.y;
    }
}

__global__ __launch_bounds__(256) void edge2_node_kernel(
    const float* __restrict__ att, const float* __restrict__ bo,
    float* __restrict__ out)
{
    int node = (blockIdx.x * 256 + threadIdx.x) >> 5;
    if (node >= NN) return;
    int lane = threadIdx.x & 31;
    int cb = lane * 8;
    int cw = (lane & 7) * 8;

    float xr[8], a[8];
    half8_to_f(g_xr2h + (size_t)node * HN2 + cb, xr);
    float4 af0 = *(const float4*)(att + cb);
    float4 af1 = *(const float4*)(att + cb + 4);
    a[0] = af0.x; a[1] = af0.y; a[2] = af0.z; a[3] = af0.w;
    a[4] = af1.x; a[5] = af1.y; a[6] = af1.z; a[7] = af1.w;

    float acc[8] = {};
    float den = 0.f;
    int rs = g_rs[node], re = g_rs[node + 1];
    for (int base = rs; base < re; base += 32) {
        int m = re - base;
        int sj = (lane < m) ? g_csr[base + lane] : 0;
        int jmax = (m < 32) ? m : 32;
        int j = 0;
        for (; j + 3 < jmax; j += 4) {
            int s[4];
            float xl[4][8];
            #pragma unroll
            for (int u = 0; u < 4; u++)
                s[u] = __shfl_sync(0xffffffffu, sj, j + u);
            #pragma unroll
            for (int u = 0; u < 4; u++)
                half8_to_f(g_xl2h + (size_t)s[u] * HN2 + cb, xl[u]);
            float p[4] = {0.f, 0.f, 0.f, 0.f};
            #pragma unroll
            for (int u = 0; u < 4; u++)
                #pragma unroll
                for (int k = 0; k < 8; k++)
                    p[u] = fmaf(a[k], lrelu(xl[u][k] + xr[k]), p[u]);
            #pragma unroll
            for (int u = 0; u < 4; u++) p[u] += __shfl_xor_sync(0xffffffffu, p[u], 1);
            #pragma unroll
            for (int u = 0; u < 4; u++) p[u] += __shfl_xor_sync(0xffffffffu, p[u], 2);
            #pragma unroll
            for (int u = 0; u < 4; u++) p[u] += __shfl_xor_sync(0xffffffffu, p[u], 4);
            #pragma unroll
            for (int u = 0; u < 4; u++) {
                float ex = __expf(p[u]);
                #pragma unroll
                for (int k = 0; k < 8; k++)
                    acc[k] = fmaf(ex, xl[u][k], acc[k]);
                den += ex;
            }
        }
        for (; j < jmax; j++) {
            int s0 = __shfl_sync(0xffffffffu, sj, j);
            float xlA[8];
            half8_to_f(g_xl2h + (size_t)s0 * HN2 + cb, xlA);
            float pA = 0.f;
            #pragma unroll
            for (int k = 0; k < 8; k++)
                pA = fmaf(a[k], lrelu(xlA[k] + xr[k]), pA);
            pA += __shfl_xor_sync(0xffffffffu, pA, 1);
            pA += __shfl_xor_sync(0xffffffffu, pA, 2);
            pA += __shfl_xor_sync(0xffffffffu, pA, 4);
            float exA = __expf(pA);
            #pragma unroll
            for (int k = 0; k < 8; k++)
                acc[k] = fmaf(exA, xlA[k], acc[k]);
            den += exA;
        }
    }
    float inv = 1.f / (den + 1e-16f);
    #pragma unroll
    for (int k = 0; k < 8; k++) {
        acc[k] *= inv;
        acc[k] += __shfl_xor_sync(0xffffffffu, acc[k], 8);
        acc[k] += __shfl_xor_sync(0xffffffffu, acc[k], 16);
    }
    if (lane < 8) {
        float4 o0, o1;
        float v;
        v = 0.25f * acc[0] + bo[cw + 0]; o0.x = v > 0.f ? v : 0.f;
        v = 0.25f * acc[1] + bo[cw + 1]; o0.y = v > 0.f ? v : 0.f;
        v = 0.25f * acc[2] + bo[cw + 2]; o0.z = v > 0.f ? v : 0.f;
        v = 0.25f * acc[3] + bo[cw + 3]; o0.w = v > 0.f ? v : 0.f;
        v = 0.25f * acc[4] + bo[cw + 4]; o1.x = v > 0.f ? v : 0.f;
        v = 0.25f * acc[5] + bo[cw + 5]; o1.y = v > 0.f ? v : 0.f;
        v = 0.25f * acc[6] + bo[cw + 6]; o1.z = v > 0.f ? v : 0.f;
        v = 0.25f * acc[7] + bo[cw + 7]; o1.w = v > 0.f ? v : 0.f;
        size_t off = (size_t)node * NOUT + cw;
        *(float4*)(out + off)     = o0;
        *(float4*)(out + off + 4) = o1;
    }
}

// ---------------- host orchestration ---------------------------------------
extern "C" void kernel_launch(void* const* d_in, const int* in_sizes, int n_in,
                              void* d_out, int out_size) {
    const float* x    = (const float*)d_in[0];
    const void*  ei   = d_in[1];
    const float* Wl1  = (const float*)d_in[3];
    const float* bl1  = (const float*)d_in[4];
    const float* Wr1  = (const float*)d_in[5];
    const float* br1  = (const float*)d_in[6];
    const float* att1 = (const float*)d_in[7];
    const float* bo1  = (const float*)d_in[8];
    const float* Wl2  = (const float*)d_in[9];
    const float* bl2  = (const float*)d_in[10];
    const float* Wr2  = (const float*)d_in[11];
    const float* br2  = (const float*)d_in[12];
    const float* att2 = (const float*)d_in[13];
    const float* bo2  = (const float*)d_in[14];
    float* out = (float*)d_out;

    __half *p_xl1, *p_xr1, *p_xl2, *p_xr2;
    float  *p_h;
    cudaGetSymbolAddress((void**)&p_xl1, g_xl1h);
    cudaGetSymbolAddress((void**)&p_xr1, g_xr1h);
    cudaGetSymbolAddress((void**)&p_h,   g_h);
    cudaGetSymbolAddress((void**)&p_xl2, g_xl2h);
    cudaGetSymbolAddress((void**)&p_xr2, g_xr2h);

    const int nblk = (NN + 127) / 128;   // 782

    // one-time host-side stream/event setup (no device memory involved)
    static cudaStream_t s1 = nullptr;
    static cudaEvent_t ev_fork = nullptr, ev_join = nullptr;
    if (s1 == nullptr) {
        if (cudaStreamCreateWithFlags(&s1, cudaStreamNonBlocking) != cudaSuccess) s1 = nullptr;
        if (cudaEventCreateWithFlags(&ev_fork, cudaEventDisableTiming) != cudaSuccess) ev_fork = nullptr;
        if (cudaEventCreateWithFlags(&ev_join, cudaEventDisableTiming) != cudaSuccess) ev_join = nullptr;
    }
    const bool fork = (s1 != nullptr && ev_fork != nullptr && ev_join != nullptr);
    cudaStream_t sc = fork ? s1 : (cudaStream_t)0;   // CSR-chain stream

    if (fork) {
        cudaEventRecord(ev_fork, 0);
        cudaStreamWaitEvent(s1, ev_fork, 0);
    }

    // CSR chain (side stream when available)
    detect_kernel<<<1, 32, 0, sc>>>(ei);
    init_deg_kernel<<<(NN + 255) / 256, 256, 0, sc>>>();
    convert_hist_kernel<<<(2 * EE + 255) / 256, 256, 0, sc>>>(ei);
    scan_phase1<<<SCAN_NBLK, 256, 0, sc>>>();
    scan_phase2<<<1, 32, 0, sc>>>();
    scan_phase3<<<SCAN_NBLK, 256, 0, sc>>>();
    scatter_kernel<<<(NE_TOT + 255) / 256, 256, 0, sc>>>();

    // layer-1 GEMMs (main stream) — overlap with CSR build
    gemm_tc_h<<<dim3(nblk, 1), 256>>>(x, Wl1, bl1, p_xl1, NN, HC1);
    gemm_tc_h<<<dim3(nblk, 1), 256>>>(x, Wr1, br1, p_xr1, NN, HC1);

    if (fork) {
        cudaEventRecord(ev_join, s1);
        cudaStreamWaitEvent((cudaStream_t)0, ev_join, 0);
    }

    edge1_node_kernel<<<(NN * 32 + 255) / 256, 256>>>(att1, bo1);

    gemm_tc_h<<<dim3(nblk, 4), 256>>>(p_h, Wl2, bl2, p_xl2, NN, HN2);
    gemm_tc_h<<<dim3(nblk, 4), 256>>>(p_h, Wr2, br2, p_xr2, NN, HN2);

    edge2_node_kernel<<<(NN * 32 + 255) / 256, 256>>>(att2, bo2, out);
}

// round 7
// speedup vs baseline: 1.1879x; 1.1879x over previous
#include <cuda_runtime.h>
#include <cuda_fp16.h>
#include <cstdint>

#define NN 100000
#define EE 1600000
#define NE_TOT (EE + NN)          // edges incl. self loops
#define H4 4
#define HC1 64                     // H*C1 (layer1 per-node feat)
#define NOUT 64
#define HN2 256                    // H*NOUT (layer2 per-node feat)
#define NEG_SLOPE 0.2f

#define SCAN_CHUNK 2048
#define SCAN_NBLK ((NN + SCAN_CHUNK - 1) / SCAN_CHUNK)   // 49

// ---------------- scratch (device globals; no allocation allowed) ----------
__device__ __half g_xl1h[(size_t)NN * HC1];
__device__ __half g_xr1h[(size_t)NN * HC1];
__device__ float  g_h   [(size_t)NN * HC1];
__device__ __half g_xl2h[(size_t)NN * HN2];
__device__ __half g_xr2h[(size_t)NN * HN2];
__device__ int    g_eidx[2 * EE];
__device__ int    g_is64;
__device__ int    g_deg[NN];
__device__ int    g_rs [NN + 1];
__device__ int    g_cur[NN];
__device__ int    g_csr[NE_TOT];
__device__ int    g_bsum[SCAN_NBLK];

// ---------------- fused: dtype detect + deg init ----------------------------
__global__ void detect_init_kernel(const void* p) {
    int i = blockIdx.x * blockDim.x + threadIdx.x;
    if (i < NN) g_deg[i] = 1;                    // self loop
    if (i == 0) {
        const long long* q = (const long long*)p;
        int is64 = 1;
        for (int t = 0; t < 256; t++) {
            long long v = q[t];
            if (v < 0 || v >= NN) { is64 = 0; break; }
        }
        g_is64 = is64;
    }
}

__global__ void convert_hist_kernel(const void* p) {
    int idx = blockIdx.x * blockDim.x + threadIdx.x;
    if (idx >= 2 * EE) return;
    int v;
    if (g_is64) v = (int)((const long long*)p)[idx];
    else        v = ((const int*)p)[idx];
    g_eidx[idx] = v;
    if (idx >= EE) atomicAdd(g_deg + v, 1);
}

// ---------------- parallel exclusive scan of g_deg --------------------------
__global__ __launch_bounds__(256) void scan_phase1() {
    int t = threadIdx.x;
    int base = blockIdx.x * SCAN_CHUNK + t * 8;
    int s = 0;
    #pragma unroll
    for (int k = 0; k < 8; k++) {
        int i = base + k;
        if (i < NN) s += g_deg[i];
    }
    #pragma unroll
    for (int off = 16; off; off >>= 1)
        s += __shfl_xor_sync(0xffffffffu, s, off);
    __shared__ int ws[8];
    if ((t & 31) == 0) ws[t >> 5] = s;
    __syncthreads();
    if (t == 0) {
        int tot = 0;
        #pragma unroll
        for (int w = 0; w < 8; w++) tot += ws[w];
        g_bsum[blockIdx.x] = tot;
    }
}

// Phase 3 with inline block-offset computation (phase 2 folded in).
__global__ __launch_bounds__(256) void scan_phase3() {
    int t = threadIdx.x;
    int lane = t & 31, wid = t >> 5;
    int bx = blockIdx.x;
    __shared__ int sh_boff;
    __shared__ int wsum[2];

    // parallel sum of bsum[0..bx-1] using first 64 threads
    if (t < 64) {
        int v = (t < bx) ? g_bsum[t] : 0;
        #pragma unroll
        for (int off = 16; off; off >>= 1)
            v += __shfl_xor_sync(0xffffffffu, v, off);
        if ((t & 31) == 0) wsum[t >> 5] = v;
    }
    __syncthreads();
    if (t == 0) {
        int boff = wsum[0] + wsum[1];
        sh_boff = boff;
        if (bx == SCAN_NBLK - 1) g_rs[NN] = boff + g_bsum[bx];
    }
    __syncthreads();

    int base = bx * SCAN_CHUNK + t * 8;
    int d[8]; int s = 0;
    #pragma unroll
    for (int k = 0; k < 8; k++) {
        int i = base + k;
        d[k] = (i < NN) ? g_deg[i] : 0;
        s += d[k];
    }
    int inc = s;
    #pragma unroll
    for (int off = 1; off < 32; off <<= 1) {
        int v = __shfl_up_sync(0xffffffffu, inc, off);
        if (lane >= off) inc += v;
    }
    __shared__ int wtot[8];
    if (lane == 31) wtot[wid] = inc;
    __syncthreads();
    int woff = 0;
    #pragma unroll
    for (int w = 0; w < 8; w++) if (w < wid) woff += wtot[w];
    int run = sh_boff + woff + (inc - s);
    #pragma unroll
    for (int k = 0; k < 8; k++) {
        int i = base + k;
        if (i < NN) { g_rs[i] = run; g_cur[i] = run; }
        run += d[k];
    }
}

__global__ void scatter_kernel() {
    int idx = blockIdx.x * blockDim.x + threadIdx.x;
    if (idx >= NE_TOT) return;
    int s, d;
    if (idx < EE) { s = g_eidx[idx]; d = g_eidx[EE + idx]; }
    else          { s = idx - EE; d = s; }
    int pos = atomicAdd(g_cur + d, 1);
    g_csr[pos] = s;
}

// ---------------- dual tensor-core GEMM: Yl = X@Wl+Bl, Yr = X@Wr+Br --------
__device__ __forceinline__ unsigned f2tf32(float f) {
    unsigned u;
    asm("cvt.rna.tf32.f32 %0, %1;" : "=r"(u) : "f"(f));
    return u;
}

__device__ __forceinline__ void mma_tf32(float* c, const unsigned* a, const unsigned* b) {
    asm volatile(
        "mma.sync.aligned.m16n8k8.row.col.f32.tf32.tf32.f32 "
        "{%0,%1,%2,%3}, {%4,%5,%6,%7}, {%8,%9}, {%0,%1,%2,%3};\n"
        : "+f"(c[0]), "+f"(c[1]), "+f"(c[2]), "+f"(c[3])
        : "r"(a[0]), "r"(a[1]), "r"(a[2]), "r"(a[3]), "r"(b[0]), "r"(b[1]));
}

#define AS_PAD 76
#define GEMM_SMEM_BYTES (128 * AS_PAD * 4 + 64 * 72 * 4)   // 38912 + 18432 = 57344

__global__ __launch_bounds__(256) void gemm_tc_dual(
    const float* __restrict__ X,
    const float* __restrict__ Wl, const float* __restrict__ Bl,
    const float* __restrict__ Wr, const float* __restrict__ Br,
    __half* __restrict__ Yl, __half* __restrict__ Yr, int n, int M)
{
    extern __shared__ unsigned smem_dyn[];
    unsigned (*as_)[AS_PAD] = (unsigned(*)[AS_PAD])smem_dyn;
    unsigned (*bs)[72] = (unsigned(*)[72])(smem_dyn + 128 * AS_PAD);

    const int n0 = blockIdx.x * 128;
    const int m0 = blockIdx.y * 64;
    const int tid = threadIdx.x;
    const int lane = tid & 31, w = tid >> 5;
    const int wr = w >> 1, wc = w & 1;
    const int l4 = lane >> 2, lm4 = lane & 3;

    // load full A tile 128x64 once
    #pragma unroll
    for (int it = 0; it < 8; it++) {
        int idx = tid + it * 256;
        int r = idx >> 4, c4 = (idx & 15) * 4;
        float4 v;
        if (n0 + r < n) v = *(const float4*)&X[(size_t)(n0 + r) * 64 + c4];
        else            v = make_float4(0.f, 0.f, 0.f, 0.f);
        as_[r][c4]     = f2tf32(v.x);
        as_[r][c4 + 1] = f2tf32(v.y);
        as_[r][c4 + 2] = f2tf32(v.z);
        as_[r][c4 + 3] = f2tf32(v.w);
    }

    #pragma unroll
    for (int mat = 0; mat < 2; mat++) {
        const float* W  = mat ? Wr : Wl;
        const float* Bi = mat ? Br : Bl;
        __half* Y       = mat ? Yr : Yl;

        __syncthreads();   // A visible (mat 0) / bs safe to overwrite (mat 1)
        #pragma unroll
        for (int it = 0; it < 4; it++) {
            int idx = tid + it * 256;
            int k = idx >> 4, c4 = (idx & 15) * 4;
            float4 v = *(const float4*)&W[(size_t)k * M + m0 + c4];
            bs[k][c4]     = f2tf32(v.x);
            bs[k][c4 + 1] = f2tf32(v.y);
            bs[k][c4 + 2] = f2tf32(v.z);
            bs[k][c4 + 3] = f2tf32(v.w);
        }
        __syncthreads();

        float c[2][4][4];
        #pragma unroll
        for (int mi = 0; mi < 2; mi++)
            #pragma unroll
            for (int ni = 0; ni < 4; ni++)
                #pragma unroll
                for (int q = 0; q < 4; q++) c[mi][ni][q] = 0.f;

        #pragma unroll
        for (int kk = 0; kk < 8; kk++) {
            int k0 = kk * 8;
            unsigned a[2][4], b[4][2];
            #pragma unroll
            for (int mi = 0; mi < 2; mi++) {
                int rb = wr * 32 + mi * 16;
                a[mi][0] = as_[rb + l4][k0 + lm4];
                a[mi][1] = as_[rb + 8 + l4][k0 + lm4];
                a[mi][2] = as_[rb + l4][k0 + 4 + lm4];
                a[mi][3] = as_[rb + 8 + l4][k0 + 4 + lm4];
            }
            #pragma unroll
            for (int ni = 0; ni < 4; ni++) {
                int cb = wc * 32 + ni * 8;
                b[ni][0] = bs[k0 + lm4][cb + l4];
                b[ni][1] = bs[k0 + 4 + lm4][cb + l4];
            }
            #pragma unroll
            for (int mi = 0; mi < 2; mi++)
                #pragma unroll
                for (int ni = 0; ni < 4; ni++)
                    mma_tf32(c[mi][ni], a[mi], b[ni]);
        }

        #pragma unroll
        for (int mi = 0; mi < 2; mi++) {
            #pragma unroll
            for (int rr = 0; rr < 2; rr++) {
                int node = n0 + wr * 32 + mi * 16 + rr * 8 + l4;
                if (node < n) {
                    #pragma unroll
                    for (int ni = 0; ni < 4; ni++) {
                        int col = wc * 32 + ni * 8 + 2 * lm4;
                        float v0 = c[mi][ni][rr * 2 + 0] + Bi[m0 + col];
                        float v1 = c[mi][ni][rr * 2 + 1] + Bi[m0 + col + 1];
                        __half2 hh = __floats2half2_rn(v0, v1);
                        *(__half2*)&Y[(size_t)node * M + m0 + col] = hh;
                    }
                }
            }
        }
    }
}

__device__ __forceinline__ float lrelu(float v) { return v > 0.f ? v : NEG_SLOPE * v; }

// ---------------- layer-1: one warp per node (CSR, atomic-free) -------------
__global__ __launch_bounds__(256) void edge1_node_kernel(
    const float* __restrict__ att, const float* __restrict__ bo)
{
    int node = (blockIdx.x * 256 + threadIdx.x) >> 5;
    if (node >= NN) return;
    int lane = threadIdx.x & 31;
    int c0 = lane * 2;

    float2 xr = __half22float2(*(const __half2*)(g_xr1h + (size_t)node * HC1 + c0));
    float  a0 = att[c0], a1 = att[c0 + 1];

    float accx = 0.f, accy = 0.f, den = 0.f;
    int rs = g_rs[node], re = g_rs[node + 1];
    for (int base = rs; base < re; base += 32) {
        int m = re - base;
        int sj = (lane < m) ? g_csr[base + lane] : 0;
        int jmax = (m < 32) ? m : 32;
        int j = 0;
        for (; j + 1 < jmax; j += 2) {
            int s0 = __shfl_sync(0xffffffffu, sj, j);
            int s1 = __shfl_sync(0xffffffffu, sj, j + 1);
            float2 xlA = __half22float2(*(const __half2*)(g_xl1h + (size_t)s0 * HC1 + c0));
            float2 xlB = __half22float2(*(const __half2*)(g_xl1h + (size_t)s1 * HC1 + c0));
            float pA = fmaf(a0, lrelu(xlA.x + xr.x), a1 * lrelu(xlA.y + xr.y));
            float pB = fmaf(a0, lrelu(xlB.x + xr.x), a1 * lrelu(xlB.y + xr.y));
            pA += __shfl_xor_sync(0xffffffffu, pA, 4);
            pB += __shfl_xor_sync(0xffffffffu, pB, 4);
            pA += __shfl_xor_sync(0xffffffffu, pA, 2);
            pB += __shfl_xor_sync(0xffffffffu, pB, 2);
            pA += __shfl_xor_sync(0xffffffffu, pA, 1);
            pB += __shfl_xor_sync(0xffffffffu, pB, 1);
            float exA = __expf(pA);
            float exB = __expf(pB);
            accx = fmaf(exA, xlA.x, accx); accy = fmaf(exA, xlA.y, accy);
            accx = fmaf(exB, xlB.x, accx); accy = fmaf(exB, xlB.y, accy);
            den += exA + exB;
        }
        if (j < jmax) {
            int s0 = __shfl_sync(0xffffffffu, sj, j);
            float2 xlA = __half22float2(*(const __half2*)(g_xl1h + (size_t)s0 * HC1 + c0));
            float pA = fmaf(a0, lrelu(xlA.x + xr.x), a1 * lrelu(xlA.y + xr.y));
            pA += __shfl_xor_sync(0xffffffffu, pA, 4);
            pA += __shfl_xor_sync(0xffffffffu, pA, 2);
            pA += __shfl_xor_sync(0xffffffffu, pA, 1);
            float exA = __expf(pA);
            accx = fmaf(exA, xlA.x, accx); accy = fmaf(exA, xlA.y, accy);
            den += exA;
        }
    }
    float inv = 1.f / (den + 1e-16f);
    float v0 = accx * inv + bo[c0];
    float v1 = accy * inv + bo[c0 + 1];
    size_t o = (size_t)node * HC1 + c0;
    g_h[o]     = v0 > 0.f ? v0 : 0.f;
    g_h[o + 1] = v1 > 0.f ? v1 : 0.f;
}

// ---------------- layer-2: one warp per node, half2 score path --------------
__device__ __forceinline__ float score_h2(const __half2* xl, const __half2* hr,
                                          const __half2* ah, __half2 neg2) {
    __half2 p2 = __float2half2_rn(0.f);
    #pragma unroll
    for (int i = 0; i < 4; i++) {
        __half2 s = __hadd2(xl[i], hr[i]);
        __half2 e = __hmax2(s, __hmul2(s, neg2));
        p2 = __hfma2(ah[i], e, p2);
    }
    float2 pf = __half22float2(p2);
    return pf.x + pf.y;
}

__global__ __launch_bounds__(256) void edge2_node_kernel(
    const float* __restrict__ att, const float* __restrict__ bo,
    float* __restrict__ out)
{
    int node = (blockIdx.x * 256 + threadIdx.x) >> 5;
    if (node >= NN) return;
    int lane = threadIdx.x & 31;
    int cb = lane * 8;
    int cw = (lane & 7) * 8;

    uint4 xr_raw = *(const uint4*)(g_xr2h + (size_t)node * HN2 + cb);
    __half2 hr[4];
    hr[0] = ((const __half2*)&xr_raw)[0]; hr[1] = ((const __half2*)&xr_raw)[1];
    hr[2] = ((const __half2*)&xr_raw)[2]; hr[3] = ((const __half2*)&xr_raw)[3];

    float4 af0 = *(const float4*)(att + cb);
    float4 af1 = *(const float4*)(att + cb + 4);
    __half2 ah[4] = { __floats2half2_rn(af0.x, af0.y), __floats2half2_rn(af0.z, af0.w),
                      __floats2half2_rn(af1.x, af1.y), __floats2half2_rn(af1.z, af1.w) };
    const __half2 neg2 = __float2half2_rn(NEG_SLOPE);

    float acc[8] = {};
    float den = 0.f;
    int rs = g_rs[node], re = g_rs[node + 1];
    for (int base = rs; base < re; base += 32) {
        int m = re - base;
        int sj = (lane < m) ? g_csr[base + lane] : 0;
        int jmax = (m < 32) ? m : 32;
        int j = 0;
        for (; j + 1 < jmax; j += 2) {
            int s0 = __shfl_sync(0xffffffffu, sj, j);
            int s1 = __shfl_sync(0xffffffffu, sj, j + 1);
            uint4 rA = *(const uint4*)(g_xl2h + (size_t)s0 * HN2 + cb);
            uint4 rB = *(const uint4*)(g_xl2h + (size_t)s1 * HN2 + cb);
            float pA = score_h2((const __half2*)&rA, hr, ah, neg2);
            float pB = score_h2((const __half2*)&rB, hr, ah, neg2);
            pA += __shfl_xor_sync(0xffffffffu, pA, 1);
            pB += __shfl_xor_sync(0xffffffffu, pB, 1);
            pA += __shfl_xor_sync(0xffffffffu, pA, 2);
            pB += __shfl_xor_sync(0xffffffffu, pB, 2);
            pA += __shfl_xor_sync(0xffffffffu, pA, 4);
            pB += __shfl_xor_sync(0xffffffffu, pB, 4);
            float exA = __expf(pA);
            float exB = __expf(pB);
            #pragma unroll
            for (int i = 0; i < 4; i++) {
                float2 fA = __half22float2(((const __half2*)&rA)[i]);
                float2 fB = __half22float2(((const __half2*)&rB)[i]);
                acc[2*i]   = fmaf(exA, fA.x, acc[2*i]);
                acc[2*i+1] = fmaf(exA, fA.y, acc[2*i+1]);
                acc[2*i]   = fmaf(exB, fB.x, acc[2*i]);
                acc[2*i+1] = fmaf(exB, fB.y, acc[2*i+1]);
            }
            den += exA + exB;
        }
        if (j < jmax) {
            int s0 = __shfl_sync(0xffffffffu, sj, j);
            uint4 rA = *(const uint4*)(g_xl2h + (size_t)s0 * HN2 + cb);
            float pA = score_h2((const __half2*)&rA, hr, ah, neg2);
            pA += __shfl_xor_sync(0xffffffffu, pA, 1);
            pA += __shfl_xor_sync(0xffffffffu, pA, 2);
            pA += __shfl_xor_sync(0xffffffffu, pA, 4);
            float exA = __expf(pA);
            #pragma unroll
            for (int i = 0; i < 4; i++) {
                float2 fA = __half22float2(((const __half2*)&rA)[i]);
                acc[2*i]   = fmaf(exA, fA.x, acc[2*i]);
                acc[2*i+1] = fmaf(exA, fA.y, acc[2*i+1]);
            }
            den += exA;
        }
    }
    float inv = 1.f / (den + 1e-16f);
    #pragma unroll
    for (int k = 0; k < 8; k++) {
        acc[k] *= inv;
        acc[k] += __shfl_xor_sync(0xffffffffu, acc[k], 8);
        acc[k] += __shfl_xor_sync(0xffffffffu, acc[k], 16);
    }
    if (lane < 8) {
        float4 o0, o1;
        float v;
        v = 0.25f * acc[0] + bo[cw + 0]; o0.x = v > 0.f ? v : 0.f;
        v = 0.25f * acc[1] + bo[cw + 1]; o0.y = v > 0.f ? v : 0.f;
        v = 0.25f * acc[2] + bo[cw + 2]; o0.z = v > 0.f ? v : 0.f;
        v = 0.25f * acc[3] + bo[cw + 3]; o0.w = v > 0.f ? v : 0.f;
        v = 0.25f * acc[4] + bo[cw + 4]; o1.x = v > 0.f ? v : 0.f;
        v = 0.25f * acc[5] + bo[cw + 5]; o1.y = v > 0.f ? v : 0.f;
        v = 0.25f * acc[6] + bo[cw + 6]; o1.z = v > 0.f ? v : 0.f;
        v = 0.25f * acc[7] + bo[cw + 7]; o1.w = v > 0.f ? v : 0.f;
        size_t off = (size_t)node * NOUT + cw;
        *(float4*)(out + off)     = o0;
        *(float4*)(out + off + 4) = o1;
    }
}

// ---------------- host orchestration ---------------------------------------
extern "C" void kernel_launch(void* const* d_in, const int* in_sizes, int n_in,
                              void* d_out, int out_size) {
    const float* x    = (const float*)d_in[0];
    const void*  ei   = d_in[1];
    const float* Wl1  = (const float*)d_in[3];
    const float* bl1  = (const float*)d_in[4];
    const float* Wr1  = (const float*)d_in[5];
    const float* br1  = (const float*)d_in[6];
    const float* att1 = (const float*)d_in[7];
    const float* bo1  = (const float*)d_in[8];
    const float* Wl2  = (const float*)d_in[9];
    const float* bl2  = (const float*)d_in[10];
    const float* Wr2  = (const float*)d_in[11];
    const float* br2  = (const float*)d_in[12];
    const float* att2 = (const float*)d_in[13];
    const float* bo2  = (const float*)d_in[14];
    float* out = (float*)d_out;

    __half *p_xl1, *p_xr1, *p_xl2, *p_xr2;
    float  *p_h;
    cudaGetSymbolAddress((void**)&p_xl1, g_xl1h);
    cudaGetSymbolAddress((void**)&p_xr1, g_xr1h);
    cudaGetSymbolAddress((void**)&p_h,   g_h);
    cudaGetSymbolAddress((void**)&p_xl2, g_xl2h);
    cudaGetSymbolAddress((void**)&p_xr2, g_xr2h);

    cudaFuncSetAttribute(gemm_tc_dual,
                         cudaFuncAttributeMaxDynamicSharedMemorySize, GEMM_SMEM_BYTES);

    const int nblk = (NN + 127) / 128;   // 782

    static cudaStream_t s1 = nullptr;
    static cudaEvent_t ev_fork = nullptr, ev_join = nullptr;
    if (s1 == nullptr) {
        if (cudaStreamCreateWithFlags(&s1, cudaStreamNonBlocking) != cudaSuccess) s1 = nullptr;
        if (cudaEventCreateWithFlags(&ev_fork, cudaEventDisableTiming) != cudaSuccess) ev_fork = nullptr;
        if (cudaEventCreateWithFlags(&ev_join, cudaEventDisableTiming) != cudaSuccess) ev_join = nullptr;
    }
    const bool fork = (s1 != nullptr && ev_fork != nullptr && ev_join != nullptr);
    cudaStream_t sc = fork ? s1 : (cudaStream_t)0;

    if (fork) {
        cudaEventRecord(ev_fork, 0);
        cudaStreamWaitEvent(s1, ev_fork, 0);
    }

    // CSR chain
    detect_init_kernel<<<(NN + 255) / 256, 256, 0, sc>>>(ei);
    convert_hist_kernel<<<(2 * EE + 255) / 256, 256, 0, sc>>>(ei);
    scan_phase1<<<SCAN_NBLK, 256, 0, sc>>>();
    scan_phase3<<<SCAN_NBLK, 256, 0, sc>>>();
    scatter_kernel<<<(NE_TOT + 255) / 256, 256, 0, sc>>>();

    // layer-1 dual GEMM (main stream, overlaps CSR build)
    gemm_tc_dual<<<dim3(nblk, 1), 256, GEMM_SMEM_BYTES>>>(
        x, Wl1, bl1, Wr1, br1, p_xl1, p_xr1, NN, HC1);

    if (fork) {
        cudaEventRecord(ev_join, s1);
        cudaStreamWaitEvent((cudaStream_t)0, ev_join, 0);
    }

    edge1_node_kernel<<<(NN * 32 + 255) / 256, 256>>>(att1, bo1);

    gemm_tc_dual<<<dim3(nblk, 4), 256, GEMM_SMEM_BYTES>>>(
        p_h, Wl2, bl2, Wr2, br2, p_xl2, p_xr2, NN, HN2);

    edge2_node_kernel<<<(NN * 32 + 255) / 256, 256>>>(att2, bo2, out);
}

// round 8
// speedup vs baseline: 1.2485x; 1.0510x over previous
#include <cuda_runtime.h>
#include <cuda_fp16.h>
#include <cstdint>

#define NN 100000
#define EE 1600000
#define NE_TOT (EE + NN)          // edges incl. self loops
#define H4 4
#define HC1 64                     // H*C1 (layer1 per-node feat)
#define NOUT 64
#define HN2 256                    // H*NOUT (layer2 per-node feat)
#define NEG_SLOPE 0.2f

#define SCAN_CHUNK 2048
#define SCAN_NBLK ((NN + SCAN_CHUNK - 1) / SCAN_CHUNK)   // 49

// ---------------- scratch (device globals; no allocation allowed) ----------
__device__ __half g_xl1h[(size_t)NN * HC1];
__device__ __half g_xr1h[(size_t)NN * HC1];
__device__ float  g_h   [(size_t)NN * HC1];
__device__ __half g_xl2h[(size_t)NN * HN2];
__device__ __half g_xr2h[(size_t)NN * HN2];
__device__ int    g_is64;
__device__ int    g_deg[NN];
__device__ int    g_rs [NN + 1];
__device__ int    g_cur[NN];
__device__ int    g_csr[NE_TOT];
__device__ int    g_bsum[SCAN_NBLK];

// ---------------- fused: dtype detect + deg init ----------------------------
__global__ void detect_init_kernel(const void* p) {
    int i = blockIdx.x * blockDim.x + threadIdx.x;
    if (i < NN) g_deg[i] = 1;                    // self loop
    if (i == 0) {
        const long long* q = (const long long*)p;
        int is64 = 1;
        for (int t = 0; t < 256; t++) {
            long long v = q[t];
            if (v < 0 || v >= NN) { is64 = 0; break; }
        }
        g_is64 = is64;
    }
}

// histogram of dst, reading the input edge index directly
__global__ void hist_kernel(const void* p) {
    int idx = blockIdx.x * blockDim.x + threadIdx.x;
    if (idx >= EE) return;
    int d;
    if (g_is64) d = (int)((const long long*)p)[EE + idx];
    else        d = ((const int*)p)[EE + idx];
    atomicAdd(g_deg + d, 1);
}

// ---------------- parallel exclusive scan of g_deg --------------------------
__global__ __launch_bounds__(256) void scan_phase1() {
    int t = threadIdx.x;
    int base = blockIdx.x * SCAN_CHUNK + t * 8;
    int s = 0;
    #pragma unroll
    for (int k = 0; k < 8; k++) {
        int i = base + k;
        if (i < NN) s += g_deg[i];
    }
    #pragma unroll
    for (int off = 16; off; off >>= 1)
        s += __shfl_xor_sync(0xffffffffu, s, off);
    __shared__ int ws[8];
    if ((t & 31) == 0) ws[t >> 5] = s;
    __syncthreads();
    if (t == 0) {
        int tot = 0;
        #pragma unroll
        for (int w = 0; w < 8; w++) tot += ws[w];
        g_bsum[blockIdx.x] = tot;
    }
}

// Phase 3 with inline block-offset computation.
__global__ __launch_bounds__(256) void scan_phase3() {
    int t = threadIdx.x;
    int lane = t & 31, wid = t >> 5;
    int bx = blockIdx.x;
    __shared__ int sh_boff;
    __shared__ int wsum[2];

    if (t < 64) {
        int v = (t < bx) ? g_bsum[t] : 0;
        #pragma unroll
        for (int off = 16; off; off >>= 1)
            v += __shfl_xor_sync(0xffffffffu, v, off);
        if ((t & 31) == 0) wsum[t >> 5] = v;
    }
    __syncthreads();
    if (t == 0) {
        int boff = wsum[0] + wsum[1];
        sh_boff = boff;
        if (bx == SCAN_NBLK - 1) g_rs[NN] = boff + g_bsum[bx];
    }
    __syncthreads();

    int base = bx * SCAN_CHUNK + t * 8;
    int d[8]; int s = 0;
    #pragma unroll
    for (int k = 0; k < 8; k++) {
        int i = base + k;
        d[k] = (i < NN) ? g_deg[i] : 0;
        s += d[k];
    }
    int inc = s;
    #pragma unroll
    for (int off = 1; off < 32; off <<= 1) {
        int v = __shfl_up_sync(0xffffffffu, inc, off);
        if (lane >= off) inc += v;
    }
    __shared__ int wtot[8];
    if (lane == 31) wtot[wid] = inc;
    __syncthreads();
    int woff = 0;
    #pragma unroll
    for (int w = 0; w < 8; w++) if (w < wid) woff += wtot[w];
    int run = sh_boff + woff + (inc - s);
    #pragma unroll
    for (int k = 0; k < 8; k++) {
        int i = base + k;
        if (i < NN) { g_rs[i] = run; g_cur[i] = run; }
        run += d[k];
    }
}

// scatter reads the input edge index directly (no staging array)
__global__ void scatter_kernel(const void* p) {
    int idx = blockIdx.x * blockDim.x + threadIdx.x;
    if (idx >= NE_TOT) return;
    int s, d;
    if (idx < EE) {
        if (g_is64) {
            s = (int)((const long long*)p)[idx];
            d = (int)((const long long*)p)[EE + idx];
        } else {
            s = ((const int*)p)[idx];
            d = ((const int*)p)[EE + idx];
        }
    } else { s = idx - EE; d = s; }
    int pos = atomicAdd(g_cur + d, 1);
    g_csr[pos] = s;
}

// ---------------- dual tensor-core GEMM: Yl = X@Wl+Bl, Yr = X@Wr+Br --------
__device__ __forceinline__ unsigned f2tf32(float f) {
    unsigned u;
    asm("cvt.rna.tf32.f32 %0, %1;" : "=r"(u) : "f"(f));
    return u;
}

__device__ __forceinline__ void mma_tf32(float* c, const unsigned* a, const unsigned* b) {
    asm volatile(
        "mma.sync.aligned.m16n8k8.row.col.f32.tf32.tf32.f32 "
        "{%0,%1,%2,%3}, {%4,%5,%6,%7}, {%8,%9}, {%0,%1,%2,%3};\n"
        : "+f"(c[0]), "+f"(c[1]), "+f"(c[2]), "+f"(c[3])
        : "r"(a[0]), "r"(a[1]), "r"(a[2]), "r"(a[3]), "r"(b[0]), "r"(b[1]));
}

#define AS_PAD 76
#define GEMM_SMEM_BYTES (128 * AS_PAD * 4 + 64 * 72 * 4)   // 57344

__global__ __launch_bounds__(256) void gemm_tc_dual(
    const float* __restrict__ X,
    const float* __restrict__ Wl, const float* __restrict__ Bl,
    const float* __restrict__ Wr, const float* __restrict__ Br,
    __half* __restrict__ Yl, __half* __restrict__ Yr, int n, int M)
{
    extern __shared__ unsigned smem_dyn[];
    unsigned (*as_)[AS_PAD] = (unsigned(*)[AS_PAD])smem_dyn;
    unsigned (*bs)[72] = (unsigned(*)[72])(smem_dyn + 128 * AS_PAD);

    const int n0 = blockIdx.x * 128;
    const int m0 = blockIdx.y * 64;
    const int tid = threadIdx.x;
    const int lane = tid & 31, w = tid >> 5;
    const int wr = w >> 1, wc = w & 1;
    const int l4 = lane >> 2, lm4 = lane & 3;

    #pragma unroll
    for (int it = 0; it < 8; it++) {
        int idx = tid + it * 256;
        int r = idx >> 4, c4 = (idx & 15) * 4;
        float4 v;
        if (n0 + r < n) v = *(const float4*)&X[(size_t)(n0 + r) * 64 + c4];
        else            v = make_float4(0.f, 0.f, 0.f, 0.f);
        as_[r][c4]     = f2tf32(v.x);
        as_[r][c4 + 1] = f2tf32(v.y);
        as_[r][c4 + 2] = f2tf32(v.z);
        as_[r][c4 + 3] = f2tf32(v.w);
    }

    #pragma unroll
    for (int mat = 0; mat < 2; mat++) {
        const float* W  = mat ? Wr : Wl;
        const float* Bi = mat ? Br : Bl;
        __half* Y       = mat ? Yr : Yl;

        __syncthreads();
        #pragma unroll
        for (int it = 0; it < 4; it++) {
            int idx = tid + it * 256;
            int k = idx >> 4, c4 = (idx & 15) * 4;
            float4 v = *(const float4*)&W[(size_t)k * M + m0 + c4];
            bs[k][c4]     = f2tf32(v.x);
            bs[k][c4 + 1] = f2tf32(v.y);
            bs[k][c4 + 2] = f2tf32(v.z);
            bs[k][c4 + 3] = f2tf32(v.w);
        }
        __syncthreads();

        float c[2][4][4];
        #pragma unroll
        for (int mi = 0; mi < 2; mi++)
            #pragma unroll
            for (int ni = 0; ni < 4; ni++)
                #pragma unroll
                for (int q = 0; q < 4; q++) c[mi][ni][q] = 0.f;

        #pragma unroll
        for (int kk = 0; kk < 8; kk++) {
            int k0 = kk * 8;
            unsigned a[2][4], b[4][2];
            #pragma unroll
            for (int mi = 0; mi < 2; mi++) {
                int rb = wr * 32 + mi * 16;
                a[mi][0] = as_[rb + l4][k0 + lm4];
                a[mi][1] = as_[rb + 8 + l4][k0 + lm4];
                a[mi][2] = as_[rb + l4][k0 + 4 + lm4];
                a[mi][3] = as_[rb + 8 + l4][k0 + 4 + lm4];
            }
            #pragma unroll
            for (int ni = 0; ni < 4; ni++) {
                int cb = wc * 32 + ni * 8;
                b[ni][0] = bs[k0 + lm4][cb + l4];
                b[ni][1] = bs[k0 + 4 + lm4][cb + l4];
            }
            #pragma unroll
            for (int mi = 0; mi < 2; mi++)
                #pragma unroll
                for (int ni = 0; ni < 4; ni++)
                    mma_tf32(c[mi][ni], a[mi], b[ni]);
        }

        #pragma unroll
        for (int mi = 0; mi < 2; mi++) {
            #pragma unroll
            for (int rr = 0; rr < 2; rr++) {
                int node = n0 + wr * 32 + mi * 16 + rr * 8 + l4;
                if (node < n) {
                    #pragma unroll
                    for (int ni = 0; ni < 4; ni++) {
                        int col = wc * 32 + ni * 8 + 2 * lm4;
                        float v0 = c[mi][ni][rr * 2 + 0] + Bi[m0 + col];
                        float v1 = c[mi][ni][rr * 2 + 1] + Bi[m0 + col + 1];
                        __half2 hh = __floats2half2_rn(v0, v1);
                        *(__half2*)&Y[(size_t)node * M + m0 + col] = hh;
                    }
                }
            }
        }
    }
}

// half2 score: dot(att, lrelu(xl + xr)) over 8 channels
__device__ __forceinline__ float score_h2(const __half2* xl, const __half2* hr,
                                          const __half2* ah, __half2 neg2) {
    __half2 p2 = __float2half2_rn(0.f);
    #pragma unroll
    for (int i = 0; i < 4; i++) {
        __half2 s = __hadd2(xl[i], hr[i]);
        __half2 e = __hmax2(s, __hmul2(s, neg2));
        p2 = __hfma2(ah[i], e, p2);
    }
    float2 pf = __half22float2(p2);
    return pf.x + pf.y;
}

// ---------------- layer-1: one warp per node, 4 edges per iteration ---------
// lane l: edge group g = l>>3, channel base c8 = (l&7)*8 (within 64 channels).
// Head = c8>>4 (16 ch per head = 2 lanes); pair-reduce via shfl_xor(1).
__global__ __launch_bounds__(256) void edge1_node_kernel(
    const float* __restrict__ att, const float* __restrict__ bo)
{
    int node = (blockIdx.x * 256 + threadIdx.x) >> 5;
    if (node >= NN) return;
    int lane = threadIdx.x & 31;
    int g  = lane >> 3;
    int c8 = (lane & 7) * 8;

    uint4 xr_raw = *(const uint4*)(g_xr1h + (size_t)node * HC1 + c8);
    __half2 hr[4];
    hr[0] = ((const __half2*)&xr_raw)[0]; hr[1] = ((const __half2*)&xr_raw)[1];
    hr[2] = ((const __half2*)&xr_raw)[2]; hr[3] = ((const __half2*)&xr_raw)[3];

    float4 af0 = *(const float4*)(att + c8);
    float4 af1 = *(const float4*)(att + c8 + 4);
    __half2 ah[4] = { __floats2half2_rn(af0.x, af0.y), __floats2half2_rn(af0.z, af0.w),
                      __floats2half2_rn(af1.x, af1.y), __floats2half2_rn(af1.z, af1.w) };
    const __half2 neg2 = __float2half2_rn(NEG_SLOPE);

    float acc[8] = {};
    float den = 0.f;
    int rs = g_rs[node], re = g_rs[node + 1];
    for (int base = rs; base < re; base += 32) {
        int m = re - base;
        int sj = (lane < m) ? g_csr[base + lane] : 0;
        int jmax = (m < 32) ? m : 32;
        for (int j = 0; j < jmax; j += 4) {
            int idx_e = j + g;
            bool valid = idx_e < jmax;
            int s = __shfl_sync(0xffffffffu, sj, valid ? idx_e : 0);
            uint4 rA = *(const uint4*)(g_xl1h + (size_t)s * HC1 + c8);
            float p = score_h2((const __half2*)&rA, hr, ah, neg2);
            p += __shfl_xor_sync(0xffffffffu, p, 1);   // 16-ch head reduce
            float ex = valid ? __expf(p) : 0.f;
            #pragma unroll
            for (int i = 0; i < 4; i++) {
                float2 f = __half22float2(((const __half2*)&rA)[i]);
                acc[2*i]   = fmaf(ex, f.x, acc[2*i]);
                acc[2*i+1] = fmaf(ex, f.y, acc[2*i+1]);
            }
            den += ex;
        }
    }
    // combine the 4 edge groups (same channels, same head)
    #pragma unroll
    for (int k = 0; k < 8; k++) {
        acc[k] += __shfl_xor_sync(0xffffffffu, acc[k], 8);
        acc[k] += __shfl_xor_sync(0xffffffffu, acc[k], 16);
    }
    den += __shfl_xor_sync(0xffffffffu, den, 8);
    den += __shfl_xor_sync(0xffffffffu, den, 16);

    if (g == 0) {
        float inv = 1.f / (den + 1e-16f);
        float4 o0, o1;
        float v;
        v = acc[0] * inv + bo[c8 + 0]; o0.x = v > 0.f ? v : 0.f;
        v = acc[1] * inv + bo[c8 + 1]; o0.y = v > 0.f ? v : 0.f;
        v = acc[2] * inv + bo[c8 + 2]; o0.z = v > 0.f ? v : 0.f;
        v = acc[3] * inv + bo[c8 + 3]; o0.w = v > 0.f ? v : 0.f;
        v = acc[4] * inv + bo[c8 + 4]; o1.x = v > 0.f ? v : 0.f;
        v = acc[5] * inv + bo[c8 + 5]; o1.y = v > 0.f ? v : 0.f;
        v = acc[6] * inv + bo[c8 + 6]; o1.z = v > 0.f ? v : 0.f;
        v = acc[7] * inv + bo[c8 + 7]; o1.w = v > 0.f ? v : 0.f;
        size_t o = (size_t)node * HC1 + c8;
        *(float4*)(g_h + o)     = o0;
        *(float4*)(g_h + o + 4) = o1;
    }
}

// ---------------- layer-2: one warp per node, half2 score path --------------
__global__ __launch_bounds__(256) void edge2_node_kernel(
    const float* __restrict__ att, const float* __restrict__ bo,
    float* __restrict__ out)
{
    int node = (blockIdx.x * 256 + threadIdx.x) >> 5;
    if (node >= NN) return;
    int lane = threadIdx.x & 31;
    int cb = lane * 8;
    int cw = (lane & 7) * 8;

    uint4 xr_raw = *(const uint4*)(g_xr2h + (size_t)node * HN2 + cb);
    __half2 hr[4];
    hr[0] = ((const __half2*)&xr_raw)[0]; hr[1] = ((const __half2*)&xr_raw)[1];
    hr[2] = ((const __half2*)&xr_raw)[2]; hr[3] = ((const __half2*)&xr_raw)[3];

    float4 af0 = *(const float4*)(att + cb);
    float4 af1 = *(const float4*)(att + cb + 4);
    __half2 ah[4] = { __floats2half2_rn(af0.x, af0.y), __floats2half2_rn(af0.z, af0.w),
                      __floats2half2_rn(af1.x, af1.y), __floats2half2_rn(af1.z, af1.w) };
    const __half2 neg2 = __float2half2_rn(NEG_SLOPE);

    float acc[8] = {};
    float den = 0.f;
    int rs = g_rs[node], re = g_rs[node + 1];
    for (int base = rs; base < re; base += 32) {
        int m = re - base;
        int sj = (lane < m) ? g_csr[base + lane] : 0;
        int jmax = (m < 32) ? m : 32;
        int j = 0;
        for (; j + 1 < jmax; j += 2) {
            int s0 = __shfl_sync(0xffffffffu, sj, j);
            int s1 = __shfl_sync(0xffffffffu, sj, j + 1);
            uint4 rA = *(const uint4*)(g_xl2h + (size_t)s0 * HN2 + cb);
            uint4 rB = *(const uint4*)(g_xl2h + (size_t)s1 * HN2 + cb);
            float pA = score_h2((const __half2*)&rA, hr, ah, neg2);
            float pB = score_h2((const __half2*)&rB, hr, ah, neg2);
            pA += __shfl_xor_sync(0xffffffffu, pA, 1);
            pB += __shfl_xor_sync(0xffffffffu, pB, 1);
            pA += __shfl_xor_sync(0xffffffffu, pA, 2);
            pB += __shfl_xor_sync(0xffffffffu, pB, 2);
            pA += __shfl_xor_sync(0xffffffffu, pA, 4);
            pB += __shfl_xor_sync(0xffffffffu, pB, 4);
            float exA = __expf(pA);
            float exB = __expf(pB);
            #pragma unroll
            for (int i = 0; i < 4; i++) {
                float2 fA = __half22float2(((const __half2*)&rA)[i]);
                float2 fB = __half22float2(((const __half2*)&rB)[i]);
                acc[2*i]   = fmaf(exA, fA.x, acc[2*i]);
                acc[2*i+1] = fmaf(exA, fA.y, acc[2*i+1]);
                acc[2*i]   = fmaf(exB, fB.x, acc[2*i]);
                acc[2*i+1] = fmaf(exB, fB.y, acc[2*i+1]);
            }
            den += exA + exB;
        }
        if (j < jmax) {
            int s0 = __shfl_sync(0xffffffffu, sj, j);
            uint4 rA = *(const uint4*)(g_xl2h + (size_t)s0 * HN2 + cb);
            float pA = score_h2((const __half2*)&rA, hr, ah, neg2);
            pA += __shfl_xor_sync(0xffffffffu, pA, 1);
            pA += __shfl_xor_sync(0xffffffffu, pA, 2);
            pA += __shfl_xor_sync(0xffffffffu, pA, 4);
            float exA = __expf(pA);
            #pragma unroll
            for (int i = 0; i < 4; i++) {
                float2 fA = __half22float2(((const __half2*)&rA)[i]);
                acc[2*i]   = fmaf(exA, fA.x, acc[2*i]);
                acc[2*i+1] = fmaf(exA, fA.y, acc[2*i+1]);
            }
            den += exA;
        }
    }
    float inv = 1.f / (den + 1e-16f);
    #pragma unroll
    for (int k = 0; k < 8; k++) {
        acc[k] *= inv;
        acc[k] += __shfl_xor_sync(0xffffffffu, acc[k], 8);
        acc[k] += __shfl_xor_sync(0xffffffffu, acc[k], 16);
    }
    if (lane < 8) {
        float4 o0, o1;
        float v;
        v = 0.25f * acc[0] + bo[cw + 0]; o0.x = v > 0.f ? v : 0.f;
        v = 0.25f * acc[1] + bo[cw + 1]; o0.y = v > 0.f ? v : 0.f;
        v = 0.25f * acc[2] + bo[cw + 2]; o0.z = v > 0.f ? v : 0.f;
        v = 0.25f * acc[3] + bo[cw + 3]; o0.w = v > 0.f ? v : 0.f;
        v = 0.25f * acc[4] + bo[cw + 4]; o1.x = v > 0.f ? v : 0.f;
        v = 0.25f * acc[5] + bo[cw + 5]; o1.y = v > 0.f ? v : 0.f;
        v = 0.25f * acc[6] + bo[cw + 6]; o1.z = v > 0.f ? v : 0.f;
        v = 0.25f * acc[7] + bo[cw + 7]; o1.w = v > 0.f ? v : 0.f;
        size_t off = (size_t)node * NOUT + cw;
        *(float4*)(out + off)     = o0;
        *(float4*)(out + off + 4) = o1;
    }
}

// ---------------- host orchestration ---------------------------------------
extern "C" void kernel_launch(void* const* d_in, const int* in_sizes, int n_in,
                              void* d_out, int out_size) {
    const float* x    = (const float*)d_in[0];
    const void*  ei   = d_in[1];
    const float* Wl1  = (const float*)d_in[3];
    const float* bl1  = (const float*)d_in[4];
    const float* Wr1  = (const float*)d_in[5];
    const float* br1  = (const float*)d_in[6];
    const float* att1 = (const float*)d_in[7];
    const float* bo1  = (const float*)d_in[8];
    const float* Wl2  = (const float*)d_in[9];
    const float* bl2  = (const float*)d_in[10];
    const float* Wr2  = (const float*)d_in[11];
    const float* br2  = (const float*)d_in[12];
    const float* att2 = (const float*)d_in[13];
    const float* bo2  = (const float*)d_in[14];
    float* out = (float*)d_out;

    __half *p_xl1, *p_xr1, *p_xl2, *p_xr2;
    float  *p_h;
    cudaGetSymbolAddress((void**)&p_xl1, g_xl1h);
    cudaGetSymbolAddress((void**)&p_xr1, g_xr1h);
    cudaGetSymbolAddress((void**)&p_h,   g_h);
    cudaGetSymbolAddress((void**)&p_xl2, g_xl2h);
    cudaGetSymbolAddress((void**)&p_xr2, g_xr2h);

    cudaFuncSetAttribute(gemm_tc_dual,
                         cudaFuncAttributeMaxDynamicSharedMemorySize, GEMM_SMEM_BYTES);

    const int nblk = (NN + 127) / 128;   // 782

    static cudaStream_t s1 = nullptr;
    static cudaEvent_t ev_fork = nullptr, ev_join = nullptr;
    if (s1 == nullptr) {
        if (cudaStreamCreateWithFlags(&s1, cudaStreamNonBlocking) != cudaSuccess) s1 = nullptr;
        if (cudaEventCreateWithFlags(&ev_fork, cudaEventDisableTiming) != cudaSuccess) ev_fork = nullptr;
        if (cudaEventCreateWithFlags(&ev_join, cudaEventDisableTiming) != cudaSuccess) ev_join = nullptr;
    }
    const bool fork = (s1 != nullptr && ev_fork != nullptr && ev_join != nullptr);
    cudaStream_t sc = fork ? s1 : (cudaStream_t)0;

    if (fork) {
        cudaEventRecord(ev_fork, 0);
        cudaStreamWaitEvent(s1, ev_fork, 0);
    }

    // CSR chain (side stream; overlaps layer-1 GEMM)
    detect_init_kernel<<<(NN + 255) / 256, 256, 0, sc>>>(ei);
    hist_kernel<<<(EE + 255) / 256, 256, 0, sc>>>(ei);
    scan_phase1<<<SCAN_NBLK, 256, 0, sc>>>();
    scan_phase3<<<SCAN_NBLK, 256, 0, sc>>>();
    scatter_kernel<<<(NE_TOT + 255) / 256, 256, 0, sc>>>(ei);

    // layer-1 dual GEMM (main stream)
    gemm_tc_dual<<<dim3(nblk, 1), 256, GEMM_SMEM_BYTES>>>(
        x, Wl1, bl1, Wr1, br1, p_xl1, p_xr1, NN, HC1);

    if (fork) {
        cudaEventRecord(ev_join, s1);
        cudaStreamWaitEvent((cudaStream_t)0, ev_join, 0);
    }

    edge1_node_kernel<<<(NN * 32 + 255) / 256, 256>>>(att1, bo1);

    gemm_tc_dual<<<dim3(nblk, 4), 256, GEMM_SMEM_BYTES>>>(
        p_h, Wl2, bl2, Wr2, br2, p_xl2, p_xr2, NN, HN2);

    edge2_node_kernel<<<(NN * 32 + 255) / 256, 256>>>(att2, bo2, out);
}